// round 12
// baseline (speedup 1.0000x reference)
#include <cuda_runtime.h>
#include <cuda_bf16.h>
#include <stdint.h>
#include <math.h>

#define BB 128
#define SS 512
#define DD 1024
#define GEN_V 50000
#define OUT_V 50257

#define NT 128                        // N columns per CTA
#define KC 32                         // K per chunk
#define NCHUNK (DD / KC)              // 32
#define NCTA ((GEN_V + NT - 1) / NT)  // 391

// ---------------------------------------------------------------------------
// Device scratch
// ---------------------------------------------------------------------------
__device__ float   g_interp[BB];
__device__ float   g_rowsum[BB];
__device__ uint8_t g_Ahi[NCHUNK * 8192];   // pre-swizzled bf16 A, 8KB per K-chunk

// ---------------------------------------------------------------------------
// Helpers (family-safe PTX only)
// ---------------------------------------------------------------------------
__device__ __forceinline__ uint32_t smem_u32(const void* p) {
    uint32_t a;
    asm("{ .reg .u64 t; cvta.to.shared.u64 t, %1; cvt.u32.u64 %0, t; }" : "=r"(a) : "l"(p));
    return a;
}

#define LDSM4(r, addr)                                                          \
    asm volatile("ldmatrix.sync.aligned.m8n8.x4.shared.b16 {%0,%1,%2,%3}, [%4];" \
        : "=r"((r)[0]), "=r"((r)[1]), "=r"((r)[2]), "=r"((r)[3]) : "r"(addr))

#define LDSM4T(r, addr)                                                               \
    asm volatile("ldmatrix.sync.aligned.m8n8.x4.trans.shared.b16 {%0,%1,%2,%3}, [%4];" \
        : "=r"((r)[0]), "=r"((r)[1]), "=r"((r)[2]), "=r"((r)[3]) : "r"(addr))

#define MMA_BF16(ac, a, b0, b1)                                                  \
    asm volatile("mma.sync.aligned.m16n8k16.row.col.f32.bf16.bf16.f32 "          \
        "{%0,%1,%2,%3}, {%4,%5,%6,%7}, {%8,%9}, {%0,%1,%2,%3};"                  \
        : "+f"((ac)[0]), "+f"((ac)[1]), "+f"((ac)[2]), "+f"((ac)[3])             \
        : "r"((a)[0]), "r"((a)[1]), "r"((a)[2]), "r"((a)[3]), "r"(b0), "r"(b1))

#define CPASYNC16(dst, src) \
    asm volatile("cp.async.ca.shared.global [%0], [%1], 16;" :: "r"(dst), "l"(src))
#define CPASYNC_COMMIT() asm volatile("cp.async.commit_group;")
#define CPASYNC_WAIT1()  asm volatile("cp.async.wait_group 1;" ::: "memory")

__device__ __forceinline__ uint32_t pack_bf16(float lo, float hi) {
    uint32_t r;
    asm("cvt.rn.bf16x2.f32 %0, %1, %2;" : "=r"(r) : "f"(hi), "f"(lo));
    return r;
}

// A chunk swizzle: o = m*64 + k*2, swizzled o ^ (((m>>1)&7)*16)
__device__ __host__ __forceinline__ uint32_t a_swz(int m, int k) {
    uint32_t o = (uint32_t)(m * 64 + k * 2);
    return o ^ ((((uint32_t)m >> 1) & 7u) << 4);
}

// ---------------------------------------------------------------------------
// Gate (also zeroes g_rowsum)
// ---------------------------------------------------------------------------
__global__ void gate_kernel(const float* __restrict__ x,
                            const float* __restrict__ Wg,
                            const float* __restrict__ bg) {
    int b = blockIdx.x;
    int tid = threadIdx.x;
    if (tid == 0) g_rowsum[b] = 0.f;
    float s = 0.f;
    for (int d = tid; d < DD; d += 256)
        s += x[b * DD + d] * Wg[d];
    __shared__ float red[256];
    red[tid] = s;
    __syncthreads();
    for (int off = 128; off > 0; off >>= 1) {
        if (tid < off) red[tid] += red[tid + off];
        __syncthreads();
    }
    if (tid == 0)
        g_interp[b] = 1.f / (1.f + expf(-(red[0] + bg[0])));
}

// ---------------------------------------------------------------------------
// Pre-convert x -> bf16 into swizzled per-chunk layout
// ---------------------------------------------------------------------------
__global__ void prepA_kernel(const float* __restrict__ x) {
    int m = blockIdx.x;
    for (int k = threadIdx.x; k < DD; k += 256) {
        float v = x[m * DD + k];
        int c = k >> 5, kk = k & 31;
        *(__nv_bfloat16*)(g_Ahi + (uint32_t)c * 8192u + a_swz(m, kk)) =
            __float2bfloat16(v);
    }
}

// ---------------------------------------------------------------------------
// Zero a slice of the output
// ---------------------------------------------------------------------------
__global__ void zero_slice_kernel(float4* __restrict__ out, int lo4, int hi4) {
    int i = lo4 + blockIdx.x * 256 + threadIdx.x;
    int stride = gridDim.x * 256;
    for (; i < hi4; i += stride) out[i] = make_float4(0.f, 0.f, 0.f, 0.f);
}

// ---------------------------------------------------------------------------
// Pure-bf16 GEMM (mma.sync), single-barrier pipelined chunks, staging hoisted
// ahead of MMA phase. 256 threads, warp grid 4m x 2n, warp tile 32x64,
// CTA tile 128x128. (BYTE-IDENTICAL to the 123.6us best kernel.)
// SMEM: bias 512 | g2o 512 | A ring 3x8K | B 2x8K
// ---------------------------------------------------------------------------
#define OFF_G2O  512
#define OFF_A    1024
#define OFF_BBF  25600
#define SMEM_SZ  41984

__global__ __launch_bounds__(256, 2) void gemm_mma_kernel(
    const float* __restrict__ W, const float* __restrict__ bias,
    const int* __restrict__ g2o, float* __restrict__ out)
{
    __shared__ __align__(1024) uint8_t smem[SMEM_SZ];
    const uint32_t sb = smem_u32(smem);

    const int tid = threadIdx.x;
    const int wid = tid >> 5;
    const int lid = tid & 31;
    const int wm = wid >> 1;          // 0..3 (M)
    const int wn = wid & 1;           // 0..1 (N)
    const int n0 = blockIdx.x * NT;

    float* sBias = (float*)(smem);
    int*   sG2O  = (int*)(smem + OFF_G2O);

    if (tid < NT) {
        int gn = n0 + tid;
        bool ok = gn < GEN_V;
        sBias[tid] = ok ? bias[gn] : 0.f;
        sG2O[tid]  = ok ? g2o[gn] : 0;
    }

    // ---- B loader assignment: 2 k-rows x 8 n per thread ----
    const int bk0 = tid >> 4;           // 0..15
    const int bk1 = bk0 + 16;           // 16..31
    const int ng  = (tid & 15) * 8;     // n offset (0..120)
    const bool bok = (n0 + ng) < GEN_V;

    float4 pf[4];   // k0: pf[0..1], k1: pf[2..3]

    auto loadB = [&](int c) {
        const float* p0 = W + (size_t)(c * KC + bk0) * GEN_V + n0 + ng;
        const float* p1 = W + (size_t)(c * KC + bk1) * GEN_V + n0 + ng;
        if (bok) {
            pf[0] = *(const float4*)(p0);
            pf[1] = *(const float4*)(p0 + 4);
            pf[2] = *(const float4*)(p1);
            pf[3] = *(const float4*)(p1 + 4);
        } else {
            pf[0] = pf[1] = pf[2] = pf[3] = make_float4(0.f, 0.f, 0.f, 0.f);
        }
    };

    auto storeB = [&](int buf) {
        #pragma unroll
        for (int half = 0; half < 2; half++) {
            int k = half ? bk1 : bk0;
            float4 a = pf[half * 2], b4 = pf[half * 2 + 1];
            uint32_t u[4];
            u[0] = pack_bf16(a.x, a.y);
            u[1] = pack_bf16(a.z, a.w);
            u[2] = pack_bf16(b4.x, b4.y);
            u[3] = pack_bf16(b4.z, b4.w);
            uint32_t off = (uint32_t)k * 256u +
                           (((uint32_t)ng * 2u) ^ (((uint32_t)k & 7u) << 4));
            *(uint4*)(smem + OFF_BBF + buf * 8192 + off) = *(uint4*)u;
        }
    };

    auto loadA_async = [&](int c) {
        const uint8_t* src = g_Ahi + (size_t)c * 8192 + tid * 32;
        uint32_t dst = sb + OFF_A + (c % 3) * 8192 + tid * 32;
        CPASYNC16(dst, src);
        CPASYNC16(dst + 16, src + 16);
    };

    float acc[2][8][4];
    #pragma unroll
    for (int i = 0; i < 2; i++)
        #pragma unroll
        for (int j = 0; j < 8; j++)
            #pragma unroll
            for (int q = 0; q < 4; q++)
                acc[i][j][q] = 0.f;

    // ldmatrix lane address components
    const int arow = wm * 32 + (lid & 15);
    const int akb  = (lid >> 4) << 4;
    const int bkrow_base = (lid & 15);
    const int bnoff = (lid >> 4) << 3;

    // ---- Prologue ----
    loadA_async(0); CPASYNC_COMMIT();      // group A0
    loadA_async(1); CPASYNC_COMMIT();      // group A1
    loadB(0);
    storeB(0);                              // buf0 = B(0)
    loadB(1);                               // pf = B(1)
    CPASYNC_WAIT1();                        // A0 done, A1 flying
    __syncthreads();

    #pragma unroll 1
    for (int c = 0; c < NCHUNK; c++) {
        // ---- Hoisted staging ----
        if (c + 1 < NCHUNK) {
            storeB((c + 1) & 1);            // consumes pf (chunk c+1)
            if (c + 2 < NCHUNK)
                loadB(c + 2);               // LDG -> pf, covered by MMA(c)
        }

        // ---- MMA over chunk c ----
        const uint32_t abuf = sb + OFF_A + (c % 3) * 8192;
        const uint32_t bbuf = sb + OFF_BBF + (c & 1) * 8192;
        #pragma unroll
        for (int ks = 0; ks < 2; ks++) {
            uint32_t ah[2][4];
            #pragma unroll
            for (int i = 0; i < 2; i++) {
                int row = arow + i * 16;
                uint32_t o = (uint32_t)(row * 64 + ks * 32 + akb);
                uint32_t swz = o ^ ((((uint32_t)row >> 1) & 7u) << 4);
                LDSM4(ah[i], abuf + swz);
            }
            #pragma unroll
            for (int j = 0; j < 4; j++) {
                int krow = ks * 16 + bkrow_base;
                int n = wn * 64 + j * 16 + bnoff;
                uint32_t off = (uint32_t)krow * 256u +
                               (((uint32_t)n * 2u) ^ (((uint32_t)krow & 7u) << 4));
                uint32_t bh[4];
                LDSM4T(bh, bbuf + off);
                #pragma unroll
                for (int i = 0; i < 2; i++) {
                    MMA_BF16(acc[i][j * 2 + 0], ah[i], bh[0], bh[1]);
                    MMA_BF16(acc[i][j * 2 + 1], ah[i], bh[2], bh[3]);
                }
            }
        }

        // ---- Post-MMA: A prefetch + wait + single barrier ----
        if (c + 1 < NCHUNK) {
            if (c + 2 < NCHUNK)
                loadA_async(c + 2);         // -> slot (c+2)%3
            CPASYNC_COMMIT();
            CPASYNC_WAIT1();                // A(c+1) done
            __syncthreads();
        }
    }

    // ---- Epilogue: bias + exp + direct atomic scatter + rowsum ----
    #pragma unroll
    for (int i = 0; i < 2; i++) {
        int r0 = wm * 32 + i * 16 + (lid >> 2);
        int r1 = r0 + 8;
        float s0 = 0.f, s1 = 0.f;
        #pragma unroll
        for (int j = 0; j < 8; j++) {
            int cidx = wn * 64 + j * 8 + (lid & 3) * 2;
            int gn = n0 + cidx;
            if (gn < GEN_V) {
                float b0 = sBias[cidx], b1 = sBias[cidx + 1];
                int o0 = sG2O[cidx], o1 = sG2O[cidx + 1];
                float p00 = __expf(acc[i][j][0] + b0);
                float p01 = __expf(acc[i][j][1] + b1);
                float p10 = __expf(acc[i][j][2] + b0);
                float p11 = __expf(acc[i][j][3] + b1);
                atomicAdd(out + (size_t)r0 * OUT_V + o0, p00);
                atomicAdd(out + (size_t)r0 * OUT_V + o1, p01);
                atomicAdd(out + (size_t)r1 * OUT_V + o0, p10);
                atomicAdd(out + (size_t)r1 * OUT_V + o1, p11);
                s0 += p00 + p01;
                s1 += p10 + p11;
            }
        }
        s0 += __shfl_xor_sync(0xFFFFFFFF, s0, 1);
        s0 += __shfl_xor_sync(0xFFFFFFFF, s0, 2);
        s1 += __shfl_xor_sync(0xFFFFFFFF, s1, 1);
        s1 += __shfl_xor_sync(0xFFFFFFFF, s1, 2);
        if ((lid & 3) == 0) {
            atomicAdd(&g_rowsum[r0], s0);
            atomicAdd(&g_rowsum[r1], s1);
        }
    }
}

// ---------------------------------------------------------------------------
// Rescale: out[b,:] *= interp[b] / rowsum[b]  (flat float4, row per element)
// ---------------------------------------------------------------------------
__global__ void rescale_kernel(float* __restrict__ out) {
    const long n = (long)BB * OUT_V;
    const long n4 = n >> 2;
    float4* o4 = (float4*)out;
    __shared__ float sScale[BB];
    for (int b = threadIdx.x; b < BB; b += 256)
        sScale[b] = g_interp[b] / g_rowsum[b];
    __syncthreads();
    long stride = (long)gridDim.x * 256;
    for (long i = (long)blockIdx.x * 256 + threadIdx.x; i < n4; i += stride) {
        long e = i << 2;
        int b0 = (int)(e / OUT_V);
        int b3 = (int)((e + 3) / OUT_V);
        float4 v = o4[i];
        if (b0 == b3) {
            float s = sScale[b0];
            v.x *= s; v.y *= s; v.z *= s; v.w *= s;
        } else {
            v.x *= sScale[(int)((e + 0) / OUT_V)];
            v.y *= sScale[(int)((e + 1) / OUT_V)];
            v.z *= sScale[(int)((e + 2) / OUT_V)];
            v.w *= sScale[(int)((e + 3) / OUT_V)];
        }
        o4[i] = v;
    }
}

// ---------------------------------------------------------------------------
// Scatter pointer probs (after rescale)
// ---------------------------------------------------------------------------
__global__ void scatter_ptr_kernel(const float* __restrict__ alphas,
                                   const int* __restrict__ ctx,
                                   const int* __restrict__ i2o,
                                   float* __restrict__ out) {
    int b = blockIdx.y;
    int s = blockIdx.x * 256 + threadIdx.x;
    if (s >= SS) return;
    float w = (1.f - g_interp[b]) * alphas[b * SS + s];
    int o = i2o[ctx[b * SS + s]];
    atomicAdd(&out[(size_t)b * OUT_V + o], w);
}

// ---------------------------------------------------------------------------
// Launch. Exactly 8 launches; the GEMM is global launch index 5 (0-based)
// so the harness ncu capture (-s 5 -c 1) profiles the GEMM.
// Inputs: x, alphas, W_gate, b_gate, W_gen, b_gen, ctx_inp,
//         gen_to_out, inp_to_out
// ---------------------------------------------------------------------------
extern "C" void kernel_launch(void* const* d_in, const int* in_sizes, int n_in,
                              void* d_out, int out_size) {
    const float* x      = (const float*)d_in[0];
    const float* alphas = (const float*)d_in[1];
    const float* W_gate = (const float*)d_in[2];
    const float* b_gate = (const float*)d_in[3];
    const float* W_gen  = (const float*)d_in[4];
    const float* b_gen  = (const float*)d_in[5];
    const int* ctx_inp  = (const int*)d_in[6];
    const int* g2o      = (const int*)d_in[7];
    const int* i2o      = (const int*)d_in[8];
    float* out = (float*)d_out;

    const int n4 = (BB * OUT_V) / 4;        // 1,608,224
    const int third = (n4 + 2) / 3;

    gate_kernel<<<BB, 256>>>(x, W_gate, b_gate);                 // launch 0
    prepA_kernel<<<BB, 256>>>(x);                                // launch 1
    zero_slice_kernel<<<768, 256>>>((float4*)out, 0, third);     // launch 2
    zero_slice_kernel<<<768, 256>>>((float4*)out, third, 2 * third);      // launch 3
    zero_slice_kernel<<<768, 256>>>((float4*)out, 2 * third, n4);         // launch 4
    gemm_mma_kernel<<<NCTA, 256>>>(W_gen, b_gen, g2o, out);      // launch 5  <- ncu
    rescale_kernel<<<2048, 256>>>(out);                          // launch 6
    dim3 pgrid((SS + 255) / 256, BB);
    scatter_ptr_kernel<<<pgrid, 256>>>(alphas, ctx_inp, i2o, out); // launch 7
}

// round 13
// speedup vs baseline: 1.0292x; 1.0292x over previous
#include <cuda_runtime.h>
#include <cuda_bf16.h>
#include <stdint.h>
#include <math.h>

#define BB 128
#define SS 512
#define DD 1024
#define GEN_V 50000
#define OUT_V 50257

#define NT 128                        // N columns per CTA
#define KC 64                         // K per chunk
#define NCHUNK (DD / KC)              // 16
#define NCTA ((GEN_V + NT - 1) / NT)  // 391

// ---------------------------------------------------------------------------
// Device scratch
// ---------------------------------------------------------------------------
__device__ float   g_interp[BB];
__device__ float   g_rowsum[BB];
__device__ uint8_t g_Ahi[32 * 8192];   // pre-swizzled bf16 A, 8KB per 32-k block

// ---------------------------------------------------------------------------
// Helpers (family-safe PTX only)
// ---------------------------------------------------------------------------
__device__ __forceinline__ uint32_t smem_u32(const void* p) {
    uint32_t a;
    asm("{ .reg .u64 t; cvta.to.shared.u64 t, %1; cvt.u32.u64 %0, t; }" : "=r"(a) : "l"(p));
    return a;
}

#define LDSM4(r, addr)                                                          \
    asm volatile("ldmatrix.sync.aligned.m8n8.x4.shared.b16 {%0,%1,%2,%3}, [%4];" \
        : "=r"((r)[0]), "=r"((r)[1]), "=r"((r)[2]), "=r"((r)[3]) : "r"(addr))

#define LDSM4T(r, addr)                                                               \
    asm volatile("ldmatrix.sync.aligned.m8n8.x4.trans.shared.b16 {%0,%1,%2,%3}, [%4];" \
        : "=r"((r)[0]), "=r"((r)[1]), "=r"((r)[2]), "=r"((r)[3]) : "r"(addr))

#define MMA_BF16(ac, a, b0, b1)                                                  \
    asm volatile("mma.sync.aligned.m16n8k16.row.col.f32.bf16.bf16.f32 "          \
        "{%0,%1,%2,%3}, {%4,%5,%6,%7}, {%8,%9}, {%0,%1,%2,%3};"                  \
        : "+f"((ac)[0]), "+f"((ac)[1]), "+f"((ac)[2]), "+f"((ac)[3])             \
        : "r"((a)[0]), "r"((a)[1]), "r"((a)[2]), "r"((a)[3]), "r"(b0), "r"(b1))

#define CPASYNC16(dst, src) \
    asm volatile("cp.async.ca.shared.global [%0], [%1], 16;" :: "r"(dst), "l"(src))
#define CPASYNC_COMMIT() asm volatile("cp.async.commit_group;")
#define CPASYNC_WAIT1()  asm volatile("cp.async.wait_group 1;" ::: "memory")

__device__ __forceinline__ uint32_t pack_bf16(float lo, float hi) {
    uint32_t r;
    asm("cvt.rn.bf16x2.f32 %0, %1, %2;" : "=r"(r) : "f"(hi), "f"(lo));
    return r;
}

// A block swizzle (within an 8KB 32-k block): o = m*64 + k*2, o ^ (((m>>1)&7)*16)
__device__ __host__ __forceinline__ uint32_t a_swz(int m, int k) {
    uint32_t o = (uint32_t)(m * 64 + k * 2);
    return o ^ ((((uint32_t)m >> 1) & 7u) << 4);
}

// ---------------------------------------------------------------------------
// Fused prep: blocks 0..127 gate, 128..255 prepA, 256.. zero out
// ---------------------------------------------------------------------------
__global__ void prep_kernel(const float* __restrict__ x,
                            const float* __restrict__ Wg,
                            const float* __restrict__ bg,
                            float4* __restrict__ out, int n4) {
    int blk = blockIdx.x;
    int tid = threadIdx.x;
    if (blk < BB) {
        int b = blk;
        if (tid == 0) g_rowsum[b] = 0.f;
        float s = 0.f;
        for (int d = tid; d < DD; d += 256)
            s += x[b * DD + d] * Wg[d];
        __shared__ float red[256];
        red[tid] = s;
        __syncthreads();
        for (int off = 128; off > 0; off >>= 1) {
            if (tid < off) red[tid] += red[tid + off];
            __syncthreads();
        }
        if (tid == 0)
            g_interp[b] = 1.f / (1.f + expf(-(red[0] + bg[0])));
    } else if (blk < 2 * BB) {
        int m = blk - BB;
        for (int k = tid; k < DD; k += 256) {
            float v = x[m * DD + k];
            int c = k >> 5, kk = k & 31;
            *(__nv_bfloat16*)(g_Ahi + (uint32_t)c * 8192u + a_swz(m, kk)) =
                __float2bfloat16(v);
        }
    } else {
        int i = (blk - 2 * BB) * 256 + tid;
        int stride = (gridDim.x - 2 * BB) * 256;
        for (; i < n4; i += stride) out[i] = make_float4(0.f, 0.f, 0.f, 0.f);
    }
}

// ---------------------------------------------------------------------------
// Pure-bf16 GEMM (mma.sync), KC=64 chunks with split-half B staging,
// single barrier per chunk. 256 threads, warp grid 4m x 2n, warp tile 32x64,
// CTA tile 128x128. Dynamic SMEM:
//   bias 512 | g2o 512 | A ring 3x16K | B 2x16K  = 83 KB
// ---------------------------------------------------------------------------
#define OFF_G2O  512
#define OFF_A    1024
#define OFF_BBF  (OFF_A + 3 * 16384)          // 50176
#define SMEM_SZ  (OFF_BBF + 2 * 16384)        // 82944
#define SMEM_DYN (SMEM_SZ + 1024)             // alignment slack

__global__ __launch_bounds__(256, 2) void gemm_mma_kernel(
    const float* __restrict__ W, const float* __restrict__ bias,
    const int* __restrict__ g2o, float* __restrict__ out)
{
    extern __shared__ __align__(16) uint8_t smem_raw[];
    const uint32_t sb0 = smem_u32(smem_raw);
    const uint32_t sb = (sb0 + 1023u) & ~1023u;
    uint8_t* smem = smem_raw + (sb - sb0);

    const int tid = threadIdx.x;
    const int wid = tid >> 5;
    const int lid = tid & 31;
    const int wm = wid >> 1;          // 0..3 (M)
    const int wn = wid & 1;           // 0..1 (N)
    const int n0 = blockIdx.x * NT;

    float* sBias = (float*)(smem);
    int*   sG2O  = (int*)(smem + OFF_G2O);

    if (tid < NT) {
        int gn = n0 + tid;
        bool ok = gn < GEN_V;
        sBias[tid] = ok ? bias[gn] : 0.f;
        sG2O[tid]  = ok ? g2o[gn] : 0;
    }

    // ---- B loader: per half (32 k-rows), 2 k-rows x 8 n per thread ----
    const int bk0 = tid >> 4;           // 0..15
    const int bk1 = bk0 + 16;           // 16..31
    const int ng  = (tid & 15) * 8;     // n offset (0..120)
    const bool bok = (n0 + ng) < GEN_V;

    float4 pf[4];   // bk0: pf[0..1], bk1: pf[2..3]  (one 32-k half)

    // load half h (k rows h*32 .. h*32+31) of chunk c
    auto loadBh = [&](int c, int h) {
        const float* p0 = W + (size_t)(c * KC + h * 32 + bk0) * GEN_V + n0 + ng;
        const float* p1 = W + (size_t)(c * KC + h * 32 + bk1) * GEN_V + n0 + ng;
        if (bok) {
            pf[0] = *(const float4*)(p0);
            pf[1] = *(const float4*)(p0 + 4);
            pf[2] = *(const float4*)(p1);
            pf[3] = *(const float4*)(p1 + 4);
        } else {
            pf[0] = pf[1] = pf[2] = pf[3] = make_float4(0.f, 0.f, 0.f, 0.f);
        }
    };

    auto storeBh = [&](int buf, int h) {
        #pragma unroll
        for (int half = 0; half < 2; half++) {
            int k = h * 32 + (half ? bk1 : bk0);
            float4 a = pf[half * 2], b4 = pf[half * 2 + 1];
            uint32_t u[4];
            u[0] = pack_bf16(a.x, a.y);
            u[1] = pack_bf16(a.z, a.w);
            u[2] = pack_bf16(b4.x, b4.y);
            u[3] = pack_bf16(b4.z, b4.w);
            uint32_t off = (uint32_t)k * 256u +
                           (((uint32_t)ng * 2u) ^ (((uint32_t)k & 7u) << 4));
            *(uint4*)(smem + OFF_BBF + buf * 16384 + off) = *(uint4*)u;
        }
    };

    auto loadA_async = [&](int c) {
        const uint8_t* src = g_Ahi + (size_t)c * 16384 + tid * 64;
        uint32_t dst = sb + OFF_A + (c % 3) * 16384 + tid * 64;
        CPASYNC16(dst, src);
        CPASYNC16(dst + 16, src + 16);
        CPASYNC16(dst + 32, src + 32);
        CPASYNC16(dst + 48, src + 48);
    };

    float acc[2][8][4];
    #pragma unroll
    for (int i = 0; i < 2; i++)
        #pragma unroll
        for (int j = 0; j < 8; j++)
            #pragma unroll
            for (int q = 0; q < 4; q++)
                acc[i][j][q] = 0.f;

    // ldmatrix lane address components
    const int arow = wm * 32 + (lid & 15);
    const int akb  = (lid >> 4) << 4;
    const int bkrow_base = (lid & 15);
    const int bnoff = (lid >> 4) << 3;

    // MMA over one ks-pair (ksp = 0 covers ks 0,1; ksp = 1 covers ks 2,3)
    auto mma_half = [&](uint32_t abuf, uint32_t bbuf, int ksp) {
        #pragma unroll
        for (int kss = 0; kss < 2; kss++) {
            const int ks = ksp * 2 + kss;
            uint32_t ah[2][4];
            #pragma unroll
            for (int i = 0; i < 2; i++) {
                int row = arow + i * 16;
                uint32_t o = (uint32_t)(row * 64 + (ks & 1) * 32 + akb);
                uint32_t swz = o ^ ((((uint32_t)row >> 1) & 7u) << 4);
                LDSM4(ah[i], abuf + (ks >> 1) * 8192 + swz);
            }
            #pragma unroll
            for (int j = 0; j < 4; j++) {
                int krow = ks * 16 + bkrow_base;
                int n = wn * 64 + j * 16 + bnoff;
                uint32_t off = (uint32_t)krow * 256u +
                               (((uint32_t)n * 2u) ^ (((uint32_t)krow & 7u) << 4));
                uint32_t bh[4];
                LDSM4T(bh, bbuf + off);
                #pragma unroll
                for (int i = 0; i < 2; i++) {
                    MMA_BF16(acc[i][j * 2 + 0], ah[i], bh[0], bh[1]);
                    MMA_BF16(acc[i][j * 2 + 1], ah[i], bh[2], bh[3]);
                }
            }
        }
    };

    // ---- Prologue ----
    loadA_async(0); CPASYNC_COMMIT();      // group A0
    loadA_async(1); CPASYNC_COMMIT();      // group A1
    loadBh(0, 0); storeBh(0, 0);
    loadBh(0, 1); storeBh(0, 1);            // buf0 = B(0) complete
    loadBh(1, 0);                           // pf = half0 of B(1)
    CPASYNC_WAIT1();                        // A0 done, A1 flying
    __syncthreads();

    #pragma unroll 1
    for (int c = 0; c < NCHUNK; c++) {
        const uint32_t abuf = sb + OFF_A + (c % 3) * 16384;
        const uint32_t bbuf = sb + OFF_BBF + (c & 1) * 16384;
        const int nxt = (c + 1) & 1;

        // stage half0 of B(c+1) (pf), start LDG of half1
        if (c + 1 < NCHUNK) {
            storeBh(nxt, 0);
            loadBh(c + 1, 1);
        }

        mma_half(abuf, bbuf, 0);            // ks 0,1

        // stage half1 of B(c+1), start LDG of half0 of B(c+2)
        if (c + 1 < NCHUNK) {
            storeBh(nxt, 1);
            if (c + 2 < NCHUNK)
                loadBh(c + 2, 0);
        }

        mma_half(abuf, bbuf, 1);            // ks 2,3

        // A prefetch + wait + single barrier
        if (c + 1 < NCHUNK) {
            if (c + 2 < NCHUNK)
                loadA_async(c + 2);         // -> slot (c+2)%3
            CPASYNC_COMMIT();
            CPASYNC_WAIT1();                // A(c+1) done
            __syncthreads();
        }
    }

    // ---- Epilogue: bias + exp + direct atomic scatter + rowsum ----
    #pragma unroll
    for (int i = 0; i < 2; i++) {
        int r0 = wm * 32 + i * 16 + (lid >> 2);
        int r1 = r0 + 8;
        float s0 = 0.f, s1 = 0.f;
        #pragma unroll
        for (int j = 0; j < 8; j++) {
            int cidx = wn * 64 + j * 8 + (lid & 3) * 2;
            int gn = n0 + cidx;
            if (gn < GEN_V) {
                float b0 = sBias[cidx], b1 = sBias[cidx + 1];
                int o0 = sG2O[cidx], o1 = sG2O[cidx + 1];
                float p00 = __expf(acc[i][j][0] + b0);
                float p01 = __expf(acc[i][j][1] + b1);
                float p10 = __expf(acc[i][j][2] + b0);
                float p11 = __expf(acc[i][j][3] + b1);
                atomicAdd(out + (size_t)r0 * OUT_V + o0, p00);
                atomicAdd(out + (size_t)r0 * OUT_V + o1, p01);
                atomicAdd(out + (size_t)r1 * OUT_V + o0, p10);
                atomicAdd(out + (size_t)r1 * OUT_V + o1, p11);
                s0 += p00 + p01;
                s1 += p10 + p11;
            }
        }
        s0 += __shfl_xor_sync(0xFFFFFFFF, s0, 1);
        s0 += __shfl_xor_sync(0xFFFFFFFF, s0, 2);
        s1 += __shfl_xor_sync(0xFFFFFFFF, s1, 1);
        s1 += __shfl_xor_sync(0xFFFFFFFF, s1, 2);
        if ((lid & 3) == 0) {
            atomicAdd(&g_rowsum[r0], s0);
            atomicAdd(&g_rowsum[r1], s1);
        }
    }
}

// ---------------------------------------------------------------------------
// Rescale: out[b,:] *= interp[b] / rowsum[b]  (flat float4, row per element)
// ---------------------------------------------------------------------------
__global__ void rescale_kernel(float* __restrict__ out) {
    const long n = (long)BB * OUT_V;
    const long n4 = n >> 2;
    float4* o4 = (float4*)out;
    __shared__ float sScale[BB];
    for (int b = threadIdx.x; b < BB; b += 256)
        sScale[b] = g_interp[b] / g_rowsum[b];
    __syncthreads();
    long stride = (long)gridDim.x * 256;
    for (long i = (long)blockIdx.x * 256 + threadIdx.x; i < n4; i += stride) {
        long e = i << 2;
        int b0 = (int)(e / OUT_V);
        int b3 = (int)((e + 3) / OUT_V);
        float4 v = o4[i];
        if (b0 == b3) {
            float s = sScale[b0];
            v.x *= s; v.y *= s; v.z *= s; v.w *= s;
        } else {
            v.x *= sScale[(int)((e + 0) / OUT_V)];
            v.y *= sScale[(int)((e + 1) / OUT_V)];
            v.z *= sScale[(int)((e + 2) / OUT_V)];
            v.w *= sScale[(int)((e + 3) / OUT_V)];
        }
        o4[i] = v;
    }
}

// ---------------------------------------------------------------------------
// Scatter pointer probs (after rescale)
// ---------------------------------------------------------------------------
__global__ void scatter_ptr_kernel(const float* __restrict__ alphas,
                                   const int* __restrict__ ctx,
                                   const int* __restrict__ i2o,
                                   float* __restrict__ out) {
    int b = blockIdx.y;
    int s = blockIdx.x * 256 + threadIdx.x;
    if (s >= SS) return;
    float w = (1.f - g_interp[b]) * alphas[b * SS + s];
    int o = i2o[ctx[b * SS + s]];
    atomicAdd(&out[(size_t)b * OUT_V + o], w);
}

// ---------------------------------------------------------------------------
// Launch. Inputs: x, alphas, W_gate, b_gate, W_gen, b_gen, ctx_inp,
//                 gen_to_out, inp_to_out
// ---------------------------------------------------------------------------
extern "C" void kernel_launch(void* const* d_in, const int* in_sizes, int n_in,
                              void* d_out, int out_size) {
    const float* x      = (const float*)d_in[0];
    const float* alphas = (const float*)d_in[1];
    const float* W_gate = (const float*)d_in[2];
    const float* b_gate = (const float*)d_in[3];
    const float* W_gen  = (const float*)d_in[4];
    const float* b_gen  = (const float*)d_in[5];
    const int* ctx_inp  = (const int*)d_in[6];
    const int* g2o      = (const int*)d_in[7];
    const int* i2o      = (const int*)d_in[8];
    float* out = (float*)d_out;

    cudaFuncSetAttribute(gemm_mma_kernel,
                         cudaFuncAttributeMaxDynamicSharedMemorySize, SMEM_DYN);

    prep_kernel<<<2 * BB + 1536, 256>>>(x, W_gate, b_gate,
                                        (float4*)out, (BB * OUT_V) / 4);
    gemm_mma_kernel<<<NCTA, 256, SMEM_DYN>>>(W_gen, b_gen, g2o, out);
    rescale_kernel<<<1024, 256>>>(out);
    dim3 pgrid((SS + 255) / 256, BB);
    scatter_ptr_kernel<<<pgrid, 256>>>(alphas, ctx_inp, i2o, out);
}

// round 14
// speedup vs baseline: 1.1605x; 1.1276x over previous
#include <cuda_runtime.h>
#include <cuda_bf16.h>
#include <stdint.h>
#include <math.h>

#define BB 128
#define SS 512
#define DD 1024
#define GEN_V 50000
#define OUT_V 50257

#define NT 96                         // N columns per CTA (521 CTAs -> 1.76 waves)
#define KC 32                         // K per chunk
#define NCHUNK (DD / KC)              // 32
#define NCTA ((GEN_V + NT - 1) / NT)  // 521

// ---------------------------------------------------------------------------
// Device scratch
// ---------------------------------------------------------------------------
__device__ float   g_interp[BB];
__device__ float   g_rowsum[BB];
__device__ uint8_t g_Ahi[NCHUNK * 8192];   // pre-swizzled bf16 A, 8KB per K-chunk

// ---------------------------------------------------------------------------
// Helpers (family-safe PTX only)
// ---------------------------------------------------------------------------
__device__ __forceinline__ uint32_t smem_u32(const void* p) {
    uint32_t a;
    asm("{ .reg .u64 t; cvta.to.shared.u64 t, %1; cvt.u32.u64 %0, t; }" : "=r"(a) : "l"(p));
    return a;
}

#define LDSM4(r, addr)                                                          \
    asm volatile("ldmatrix.sync.aligned.m8n8.x4.shared.b16 {%0,%1,%2,%3}, [%4];" \
        : "=r"((r)[0]), "=r"((r)[1]), "=r"((r)[2]), "=r"((r)[3]) : "r"(addr))

#define LDSM4T(r, addr)                                                               \
    asm volatile("ldmatrix.sync.aligned.m8n8.x4.trans.shared.b16 {%0,%1,%2,%3}, [%4];" \
        : "=r"((r)[0]), "=r"((r)[1]), "=r"((r)[2]), "=r"((r)[3]) : "r"(addr))

#define MMA_BF16(ac, a, b0, b1)                                                  \
    asm volatile("mma.sync.aligned.m16n8k16.row.col.f32.bf16.bf16.f32 "          \
        "{%0,%1,%2,%3}, {%4,%5,%6,%7}, {%8,%9}, {%0,%1,%2,%3};"                  \
        : "+f"((ac)[0]), "+f"((ac)[1]), "+f"((ac)[2]), "+f"((ac)[3])             \
        : "r"((a)[0]), "r"((a)[1]), "r"((a)[2]), "r"((a)[3]), "r"(b0), "r"(b1))

#define CPASYNC16(dst, src) \
    asm volatile("cp.async.ca.shared.global [%0], [%1], 16;" :: "r"(dst), "l"(src))
#define CPASYNC_COMMIT() asm volatile("cp.async.commit_group;")
#define CPASYNC_WAIT1()  asm volatile("cp.async.wait_group 1;" ::: "memory")

__device__ __forceinline__ uint32_t pack_bf16(float lo, float hi) {
    uint32_t r;
    asm("cvt.rn.bf16x2.f32 %0, %1, %2;" : "=r"(r) : "f"(hi), "f"(lo));
    return r;
}

// A chunk swizzle: o = m*64 + k*2, swizzled o ^ (((m>>1)&7)*16)
__device__ __host__ __forceinline__ uint32_t a_swz(int m, int k) {
    uint32_t o = (uint32_t)(m * 64 + k * 2);
    return o ^ ((((uint32_t)m >> 1) & 7u) << 4);
}

// ---------------------------------------------------------------------------
// Fused prep: blocks 0..127 gate, 128..255 prepA, 256.. zero out
// ---------------------------------------------------------------------------
__global__ void prep_kernel(const float* __restrict__ x,
                            const float* __restrict__ Wg,
                            const float* __restrict__ bg,
                            float4* __restrict__ out, int n4) {
    int blk = blockIdx.x;
    int tid = threadIdx.x;
    if (blk < BB) {
        int b = blk;
        if (tid == 0) g_rowsum[b] = 0.f;
        float s = 0.f;
        for (int d = tid; d < DD; d += 256)
            s += x[b * DD + d] * Wg[d];
        __shared__ float red[256];
        red[tid] = s;
        __syncthreads();
        for (int off = 128; off > 0; off >>= 1) {
            if (tid < off) red[tid] += red[tid + off];
            __syncthreads();
        }
        if (tid == 0)
            g_interp[b] = 1.f / (1.f + expf(-(red[0] + bg[0])));
    } else if (blk < 2 * BB) {
        int m = blk - BB;
        for (int k = tid; k < DD; k += 256) {
            float v = x[m * DD + k];
            int c = k >> 5, kk = k & 31;
            *(__nv_bfloat16*)(g_Ahi + (uint32_t)c * 8192u + a_swz(m, kk)) =
                __float2bfloat16(v);
        }
    } else {
        int i = (blk - 2 * BB) * 256 + tid;
        int stride = (gridDim.x - 2 * BB) * 256;
        for (; i < n4; i += stride) out[i] = make_float4(0.f, 0.f, 0.f, 0.f);
    }
}

// ---------------------------------------------------------------------------
// Pure-bf16 GEMM (mma.sync), single-barrier pipelined chunks, staging hoisted.
// 256 threads, warp grid 4m x 2n, warp tile 32x48, CTA tile 128x96.
// B smem rows keep 256B stride (cols 96..127 unused) so swizzle/LDSM
// formulas are identical to the proven NT=128 kernel.
// SMEM: bias 512 | g2o 512 | A ring 3x8K | B 2x8K
// ---------------------------------------------------------------------------
#define OFF_G2O  512
#define OFF_A    1024
#define OFF_BBF  25600
#define SMEM_SZ  41984

__global__ __launch_bounds__(256, 2) void gemm_mma_kernel(
    const float* __restrict__ W, const float* __restrict__ bias,
    const int* __restrict__ g2o, float* __restrict__ out)
{
    __shared__ __align__(1024) uint8_t smem[SMEM_SZ];
    const uint32_t sb = smem_u32(smem);

    const int tid = threadIdx.x;
    const int wid = tid >> 5;
    const int lid = tid & 31;
    const int wm = wid >> 1;          // 0..3 (M)
    const int wn = wid & 1;           // 0..1 (N)
    const int n0 = blockIdx.x * NT;

    float* sBias = (float*)(smem);
    int*   sG2O  = (int*)(smem + OFF_G2O);

    if (tid < NT) {
        int gn = n0 + tid;
        bool ok = gn < GEN_V;
        sBias[tid] = ok ? bias[gn] : 0.f;
        sG2O[tid]  = ok ? g2o[gn] : 0;
    }

    // ---- B loader: 2 k-rows x 8 n per thread; threads with ng>=96 idle ----
    const int bk0 = tid >> 4;           // 0..15
    const int bk1 = bk0 + 16;           // 16..31
    const int ng  = (tid & 15) * 8;     // n offset (0..120; active if <96)
    const bool bact = (ng < NT) && (n0 + ng < GEN_V);

    float4 pf[4];   // k0: pf[0..1], k1: pf[2..3]

    auto loadB = [&](int c) {
        const float* p0 = W + (size_t)(c * KC + bk0) * GEN_V + n0 + ng;
        const float* p1 = W + (size_t)(c * KC + bk1) * GEN_V + n0 + ng;
        if (bact) {
            pf[0] = *(const float4*)(p0);
            pf[1] = *(const float4*)(p0 + 4);
            pf[2] = *(const float4*)(p1);
            pf[3] = *(const float4*)(p1 + 4);
        } else {
            pf[0] = pf[1] = pf[2] = pf[3] = make_float4(0.f, 0.f, 0.f, 0.f);
        }
    };

    auto storeB = [&](int buf) {
        if (ng >= NT) return;           // cols 96..127 never read
        #pragma unroll
        for (int half = 0; half < 2; half++) {
            int k = half ? bk1 : bk0;
            float4 a = pf[half * 2], b4 = pf[half * 2 + 1];
            uint32_t u[4];
            u[0] = pack_bf16(a.x, a.y);
            u[1] = pack_bf16(a.z, a.w);
            u[2] = pack_bf16(b4.x, b4.y);
            u[3] = pack_bf16(b4.z, b4.w);
            uint32_t off = (uint32_t)k * 256u +
                           (((uint32_t)ng * 2u) ^ (((uint32_t)k & 7u) << 4));
            *(uint4*)(smem + OFF_BBF + buf * 8192 + off) = *(uint4*)u;
        }
    };

    auto loadA_async = [&](int c) {
        const uint8_t* src = g_Ahi + (size_t)c * 8192 + tid * 32;
        uint32_t dst = sb + OFF_A + (c % 3) * 8192 + tid * 32;
        CPASYNC16(dst, src);
        CPASYNC16(dst + 16, src + 16);
    };

    float acc[2][6][4];
    #pragma unroll
    for (int i = 0; i < 2; i++)
        #pragma unroll
        for (int j = 0; j < 6; j++)
            #pragma unroll
            for (int q = 0; q < 4; q++)
                acc[i][j][q] = 0.f;

    // ldmatrix lane address components
    const int arow = wm * 32 + (lid & 15);
    const int akb  = (lid >> 4) << 4;
    const int bkrow_base = (lid & 15);
    const int bnoff = (lid >> 4) << 3;

    // ---- Prologue ----
    loadA_async(0); CPASYNC_COMMIT();      // group A0
    loadA_async(1); CPASYNC_COMMIT();      // group A1
    loadB(0);
    storeB(0);                              // buf0 = B(0)
    loadB(1);                               // pf = B(1)
    CPASYNC_WAIT1();                        // A0 done, A1 flying
    __syncthreads();

    #pragma unroll 1
    for (int c = 0; c < NCHUNK; c++) {
        // ---- Hoisted staging ----
        if (c + 1 < NCHUNK) {
            storeB((c + 1) & 1);            // consumes pf (chunk c+1)
            if (c + 2 < NCHUNK)
                loadB(c + 2);               // LDG -> pf, covered by MMA(c)
        }

        // ---- MMA over chunk c ----
        const uint32_t abuf = sb + OFF_A + (c % 3) * 8192;
        const uint32_t bbuf = sb + OFF_BBF + (c & 1) * 8192;
        #pragma unroll
        for (int ks = 0; ks < 2; ks++) {
            uint32_t ah[2][4];
            #pragma unroll
            for (int i = 0; i < 2; i++) {
                int row = arow + i * 16;
                uint32_t o = (uint32_t)(row * 64 + ks * 32 + akb);
                uint32_t swz = o ^ ((((uint32_t)row >> 1) & 7u) << 4);
                LDSM4(ah[i], abuf + swz);
            }
            #pragma unroll
            for (int j = 0; j < 3; j++) {
                int krow = ks * 16 + bkrow_base;
                int n = wn * 48 + j * 16 + bnoff;
                uint32_t off = (uint32_t)krow * 256u +
                               (((uint32_t)n * 2u) ^ (((uint32_t)krow & 7u) << 4));
                uint32_t bh[4];
                LDSM4T(bh, bbuf + off);
                #pragma unroll
                for (int i = 0; i < 2; i++) {
                    MMA_BF16(acc[i][j * 2 + 0], ah[i], bh[0], bh[1]);
                    MMA_BF16(acc[i][j * 2 + 1], ah[i], bh[2], bh[3]);
                }
            }
        }

        // ---- Post-MMA: A prefetch + wait + single barrier ----
        if (c + 1 < NCHUNK) {
            if (c + 2 < NCHUNK)
                loadA_async(c + 2);         // -> slot (c+2)%3
            CPASYNC_COMMIT();
            CPASYNC_WAIT1();                // A(c+1) done
            __syncthreads();
        }
    }

    // ---- Epilogue: bias + exp + direct atomic scatter + rowsum ----
    #pragma unroll
    for (int i = 0; i < 2; i++) {
        int r0 = wm * 32 + i * 16 + (lid >> 2);
        int r1 = r0 + 8;
        float s0 = 0.f, s1 = 0.f;
        #pragma unroll
        for (int j = 0; j < 6; j++) {
            int cidx = wn * 48 + j * 8 + (lid & 3) * 2;
            int gn = n0 + cidx;
            if (gn < GEN_V) {
                float b0 = sBias[cidx], b1 = sBias[cidx + 1];
                int o0 = sG2O[cidx], o1 = sG2O[cidx + 1];
                float p00 = __expf(acc[i][j][0] + b0);
                float p01 = __expf(acc[i][j][1] + b1);
                float p10 = __expf(acc[i][j][2] + b0);
                float p11 = __expf(acc[i][j][3] + b1);
                atomicAdd(out + (size_t)r0 * OUT_V + o0, p00);
                atomicAdd(out + (size_t)r0 * OUT_V + o1, p01);
                atomicAdd(out + (size_t)r1 * OUT_V + o0, p10);
                atomicAdd(out + (size_t)r1 * OUT_V + o1, p11);
                s0 += p00 + p01;
                s1 += p10 + p11;
            }
        }
        s0 += __shfl_xor_sync(0xFFFFFFFF, s0, 1);
        s0 += __shfl_xor_sync(0xFFFFFFFF, s0, 2);
        s1 += __shfl_xor_sync(0xFFFFFFFF, s1, 1);
        s1 += __shfl_xor_sync(0xFFFFFFFF, s1, 2);
        if ((lid & 3) == 0) {
            atomicAdd(&g_rowsum[r0], s0);
            atomicAdd(&g_rowsum[r1], s1);
        }
    }
}

// ---------------------------------------------------------------------------
// Rescale: out[b,:] *= interp[b] / rowsum[b]  (flat float4, row per element)
// ---------------------------------------------------------------------------
__global__ void rescale_kernel(float* __restrict__ out) {
    const long n = (long)BB * OUT_V;
    const long n4 = n >> 2;
    float4* o4 = (float4*)out;
    __shared__ float sScale[BB];
    for (int b = threadIdx.x; b < BB; b += 256)
        sScale[b] = g_interp[b] / g_rowsum[b];
    __syncthreads();
    long stride = (long)gridDim.x * 256;
    for (long i = (long)blockIdx.x * 256 + threadIdx.x; i < n4; i += stride) {
        long e = i << 2;
        int b0 = (int)(e / OUT_V);
        int b3 = (int)((e + 3) / OUT_V);
        float4 v = o4[i];
        if (b0 == b3) {
            float s = sScale[b0];
            v.x *= s; v.y *= s; v.z *= s; v.w *= s;
        } else {
            v.x *= sScale[(int)((e + 0) / OUT_V)];
            v.y *= sScale[(int)((e + 1) / OUT_V)];
            v.z *= sScale[(int)((e + 2) / OUT_V)];
            v.w *= sScale[(int)((e + 3) / OUT_V)];
        }
        o4[i] = v;
    }
}

// ---------------------------------------------------------------------------
// Scatter pointer probs (after rescale)
// ---------------------------------------------------------------------------
__global__ void scatter_ptr_kernel(const float* __restrict__ alphas,
                                   const int* __restrict__ ctx,
                                   const int* __restrict__ i2o,
                                   float* __restrict__ out) {
    int b = blockIdx.y;
    int s = blockIdx.x * 256 + threadIdx.x;
    if (s >= SS) return;
    float w = (1.f - g_interp[b]) * alphas[b * SS + s];
    int o = i2o[ctx[b * SS + s]];
    atomicAdd(&out[(size_t)b * OUT_V + o], w);
}

// ---------------------------------------------------------------------------
// Launch. Inputs: x, alphas, W_gate, b_gate, W_gen, b_gen, ctx_inp,
//                 gen_to_out, inp_to_out
// ---------------------------------------------------------------------------
extern "C" void kernel_launch(void* const* d_in, const int* in_sizes, int n_in,
                              void* d_out, int out_size) {
    const float* x      = (const float*)d_in[0];
    const float* alphas = (const float*)d_in[1];
    const float* W_gate = (const float*)d_in[2];
    const float* b_gate = (const float*)d_in[3];
    const float* W_gen  = (const float*)d_in[4];
    const float* b_gen  = (const float*)d_in[5];
    const int* ctx_inp  = (const int*)d_in[6];
    const int* g2o      = (const int*)d_in[7];
    const int* i2o      = (const int*)d_in[8];
    float* out = (float*)d_out;

    prep_kernel<<<2 * BB + 1536, 256>>>(x, W_gate, b_gate,
                                        (float4*)out, (BB * OUT_V) / 4);
    gemm_mma_kernel<<<NCTA, 256>>>(W_gen, b_gen, g2o, out);
    rescale_kernel<<<1024, 256>>>(out);
    dim3 pgrid((SS + 255) / 256, BB);
    scatter_ptr_kernel<<<pgrid, 256>>>(alphas, ctx_inp, i2o, out);
}